// round 6
// baseline (speedup 1.0000x reference)
#include <cuda_runtime.h>
#include <cuda_bf16.h>
#include <math.h>
#include <stdint.h>

// ---------------------------------------------------------------------------
// SentenceEncoder round 6: mma.sync tf32x3 GEMMs (cvt.rna.tf32 fix: =r dest)
// B=8 S=1024 D=768 H=12 HD=64 FF=3072 L=12
// ---------------------------------------------------------------------------

#define NB    8
#define SEQ   1024
#define NTOK  (NB * SEQ)        // 8192
#define DM    768
#define DFF   3072
#define NH    12
#define HD    64
#define NL    12
#define DQKV  (3 * DM)          // 2304

// ------------------------- scratch (device globals) ------------------------
__device__ float g_h   [NTOK * DM];
__device__ float g_qkv [NTOK * DQKV];
__device__ float g_ctx [NTOK * DM];
__device__ float g_t1  [NTOK * DM];
__device__ float g_ao  [NTOK * DM];
__device__ float g_int [NTOK * DFF];
__device__ int   g_len [NB];

// pre-transposed + tf32-split weights ([N,K] row-major, K-major)
__device__ float g_qkvh[NL * DQKV * DM];
__device__ float g_qkvl[NL * DQKV * DM];
__device__ float g_oh  [NL * DM * DM];
__device__ float g_ol  [NL * DM * DM];
__device__ float g_ih  [NL * DFF * DM];
__device__ float g_il  [NL * DFF * DM];
__device__ float g_moh [NL * DM * DFF];
__device__ float g_mol [NL * DM * DFF];
__device__ float g_bqkv[NL * DQKV];

// ------------------------------ helpers ------------------------------------
// cvt.rna.tf32.f32 requires a b32 (register) destination -> "=r".
__device__ __forceinline__ float tf32_round(float x) {
    uint32_t u;
    asm("cvt.rna.tf32.f32 %0, %1;" : "=r"(u) : "f"(x));
    return __uint_as_float(u);
}

__device__ __forceinline__ void tf32_split(float x, float& hi, float& lo) {
    float h = tf32_round(x);
    hi = h;
    lo = tf32_round(x - h);
}

__device__ __forceinline__ float gelu_exact(float x) {
    return 0.5f * x * (1.0f + erff(x * 0.70710678118654752f));
}

__device__ __forceinline__ void mma_m16n8k8_tf32(float* c, const uint32_t* a,
                                                 const uint32_t* b) {
    asm volatile(
        "mma.sync.aligned.m16n8k8.row.col.f32.tf32.tf32.f32 "
        "{%0,%1,%2,%3}, {%4,%5,%6,%7}, {%8,%9}, {%0,%1,%2,%3};\n"
        : "+f"(c[0]), "+f"(c[1]), "+f"(c[2]), "+f"(c[3])
        : "r"(a[0]), "r"(a[1]), "r"(a[2]), "r"(a[3]), "r"(b[0]), "r"(b[1]));
}

__device__ __forceinline__ void block_reduce2(float& sum, float& sq) {
    #pragma unroll
    for (int o = 16; o > 0; o >>= 1) {
        sum += __shfl_xor_sync(0xffffffffu, sum, o);
        sq  += __shfl_xor_sync(0xffffffffu, sq, o);
    }
    __shared__ float rs[8], rq[8];
    int w = threadIdx.x >> 5;
    if ((threadIdx.x & 31) == 0) { rs[w] = sum; rq[w] = sq; }
    __syncthreads();
    sum = 0.0f; sq = 0.0f;
    #pragma unroll
    for (int i = 0; i < 8; i++) { sum += rs[i]; sq += rq[i]; }
}

__device__ __forceinline__ float block_reduce1(float v) {
    #pragma unroll
    for (int o = 16; o > 0; o >>= 1)
        v += __shfl_xor_sync(0xffffffffu, v, o);
    __shared__ float r[8];
    int w = threadIdx.x >> 5;
    if ((threadIdx.x & 31) == 0) r[w] = v;
    __syncthreads();
    float t = 0.0f;
    #pragma unroll
    for (int i = 0; i < 8; i++) t += r[i];
    return t;
}

// ----------------------- weight transpose + split --------------------------
// in: [L, K, N] (l at blockIdx.z); out hi/lo: [N, K] slices at given strides.
__global__ void transpose_split_kernel(const float* __restrict__ in,
                                       float* __restrict__ oh, float* __restrict__ ol,
                                       int K, int N, size_t inL, size_t outL) {
    __shared__ float t[32][33];
    int l = blockIdx.z;
    const float* ip = in + (size_t)l * inL;
    float* ohp = oh + (size_t)l * outL;
    float* olp = ol + (size_t)l * outL;
    int n0 = blockIdx.x << 5, k0 = blockIdx.y << 5;
    int tx = threadIdx.x & 31, ty = threadIdx.x >> 5;
    #pragma unroll
    for (int i = 0; i < 4; i++)
        t[ty + 8 * i][tx] = ip[(size_t)(k0 + ty + 8 * i) * N + n0 + tx];
    __syncthreads();
    #pragma unroll
    for (int i = 0; i < 4; i++) {
        float x = t[tx][ty + 8 * i];
        float hi, lo;
        tf32_split(x, hi, lo);
        size_t o = (size_t)(n0 + ty + 8 * i) * K + k0 + tx;
        ohp[o] = hi; olp[o] = lo;
    }
}

__global__ void biaspack_kernel(const float* __restrict__ bq,
                                const float* __restrict__ bk,
                                const float* __restrict__ bv,
                                float* __restrict__ out) {
    int l = blockIdx.x;
    for (int j = threadIdx.x; j < DQKV; j += 256) {
        int which = j / DM, r = j - which * DM;
        float v = (which == 0) ? bq[l * DM + r] :
                  (which == 1) ? bk[l * DM + r] : bv[l * DM + r];
        out[l * DQKV + j] = v;
    }
}

// ---------------------------- embeddings + LN -------------------------------
__global__ void embed_ln_kernel(const int* __restrict__ ids,
                                const float* __restrict__ we,
                                const float* __restrict__ pe,
                                const float* __restrict__ te,
                                const float* __restrict__ gam,
                                const float* __restrict__ bet,
                                float* __restrict__ out) {
    int tok = blockIdx.x;
    int s   = tok & (SEQ - 1);
    int id  = ids[tok];
    const float* wrow = we + (size_t)id * DM;
    const float* prow = pe + (size_t)s * DM;
    float x[3];
    float sum = 0.0f, sq = 0.0f;
    #pragma unroll
    for (int i = 0; i < 3; i++) {
        int d = threadIdx.x + (i << 8);
        float t = wrow[d] + prow[d] + te[d];
        x[i] = t; sum += t; sq += t * t;
    }
    block_reduce2(sum, sq);
    float mean = sum * (1.0f / DM);
    float var  = sq * (1.0f / DM) - mean * mean;
    float inv  = rsqrtf(var + 1e-12f);
    float* op = out + (size_t)tok * DM;
    #pragma unroll
    for (int i = 0; i < 3; i++) {
        int d = threadIdx.x + (i << 8);
        op[d] = (x[i] - mean) * inv * gam[d] + bet[d];
    }
}

__global__ void add_ln_kernel(const float* __restrict__ x,
                              const float* __restrict__ res,
                              const float* __restrict__ gam,
                              const float* __restrict__ bet,
                              float* __restrict__ out) {
    int tok = blockIdx.x;
    const float* xp = x   + (size_t)tok * DM;
    const float* rp = res + (size_t)tok * DM;
    float v[3];
    float sum = 0.0f, sq = 0.0f;
    #pragma unroll
    for (int i = 0; i < 3; i++) {
        int d = threadIdx.x + (i << 8);
        float t = xp[d] + rp[d];
        v[i] = t; sum += t; sq += t * t;
    }
    block_reduce2(sum, sq);
    float mean = sum * (1.0f / DM);
    float var  = sq * (1.0f / DM) - mean * mean;
    float inv  = rsqrtf(var + 1e-12f);
    float* op = out + (size_t)tok * DM;
    #pragma unroll
    for (int i = 0; i < 3; i++) {
        int d = threadIdx.x + (i << 8);
        op[d] = (v[i] - mean) * inv * gam[d] + bet[d];
    }
}

__global__ void length_kernel(const int* __restrict__ mask, int* __restrict__ len) {
    int b = blockIdx.x;
    int v = 0;
    for (int i = threadIdx.x; i < SEQ; i += 256) v += mask[b * SEQ + i];
    #pragma unroll
    for (int o = 16; o > 0; o >>= 1)
        v += __shfl_xor_sync(0xffffffffu, v, o);
    __shared__ int ri[8];
    int w = threadIdx.x >> 5;
    if ((threadIdx.x & 31) == 0) ri[w] = v;
    __syncthreads();
    if (threadIdx.x == 0) {
        int t = 0;
        #pragma unroll
        for (int i = 0; i < 8; i++) t += ri[i];
        len[b] = t;
    }
}

// ------------------------ mma.sync tf32x3 GEMM ------------------------------
// C[8192, Nout] = act( A[8192,K] @ Wt^T + bias ), Wt stored [Nout, K] hi/lo.
// Block 128x128, 8 warps (2 m x 4 n), warp tile 64x32, m16n8k8 tf32, x3 split.
// smem holds fragment-packed tiles: all consumer LDS vectorized+conflict-free.
//   A_pack  [4 kstep][8 mfrag][32 lane] float4   (16 KB each for hi, lo)
//   B_pack  [4 kstep][16 nfrag][32 lane] float2  (16 KB each for hi, lo)
#define GEMM_SMEM_MMA 65536

__global__ void __launch_bounds__(256, 1)
gemm_mma_kernel(const float* __restrict__ A,
                const float* __restrict__ Bh, const float* __restrict__ Bl,
                const float* __restrict__ bias, float* __restrict__ C,
                int K, int Nout, int act) {
    extern __shared__ __align__(16) char sm[];
    char* smAh = sm;
    char* smAl = sm + 16384;
    char* smBh = sm + 32768;
    char* smBl = sm + 49152;

    const int tid = threadIdx.x;
    const int wid = tid >> 5;
    const int l   = tid & 31;
    const int wm  = wid & 1;          // m-half (64 rows)
    const int wn  = wid >> 1;         // n-quarter (32 cols)
    const int r   = l >> 2;           // groupID
    const int tig = l & 3;            // threadID in group

    const int m0 = blockIdx.y << 7;
    const int n0 = blockIdx.x << 7;
    const int nch = K >> 5;           // 32-wide k chunks

    const float* Ag  = A  + (size_t)m0 * K;
    const float* Bhg = Bh + (size_t)n0 * K;
    const float* Blg = Bl + (size_t)n0 * K;

    // producer (s,f)/(s,g) assignments for this warp
    // A: 4 pairs, pidx = wid*4+i -> s=pidx>>3, f=pidx&7
    // B: 8 pairs, pidx = wid*8+i -> s=pidx>>4, g=pidx&15
    float ra[4][4];
    float rbh[8][2], rbl[8][2];

    // ---- stage chunk 0 into registers ----
    {
        const int kc = 0;
        #pragma unroll
        for (int i = 0; i < 4; i++) {
            int pidx = wid * 4 + i;
            int s = pidx >> 3, f = pidx & 7;
            const float* ap = Ag + (size_t)(f * 16 + r) * K + kc + s * 8 + tig;
            ra[i][0] = ap[0];
            ra[i][1] = ap[(size_t)8 * K];
            ra[i][2] = ap[4];
            ra[i][3] = ap[(size_t)8 * K + 4];
        }
        #pragma unroll
        for (int i = 0; i < 8; i++) {
            int pidx = wid * 8 + i;
            int s = pidx >> 4, g = pidx & 15;
            size_t o = (size_t)(g * 8 + r) * K + kc + s * 8 + tig;
            rbh[i][0] = Bhg[o]; rbh[i][1] = Bhg[o + 4];
            rbl[i][0] = Blg[o]; rbl[i][1] = Blg[o + 4];
        }
    }

    float acc[4][4][4];
    #pragma unroll
    for (int i = 0; i < 4; i++)
        #pragma unroll
        for (int j = 0; j < 4; j++)
            #pragma unroll
            for (int q = 0; q < 4; q++) acc[i][j][q] = 0.0f;

    for (int c = 0; c < nch; c++) {
        __syncthreads();   // previous chunk's MMA reads done
        // ---- STS: split A, pack fragments ----
        #pragma unroll
        for (int i = 0; i < 4; i++) {
            int pidx = wid * 4 + i;
            int s = pidx >> 3, f = pidx & 7;
            float4 h, lo;
            tf32_split(ra[i][0], h.x, lo.x);
            tf32_split(ra[i][1], h.y, lo.y);
            tf32_split(ra[i][2], h.z, lo.z);
            tf32_split(ra[i][3], h.w, lo.w);
            uint32_t off = (uint32_t)(((s * 8 + f) * 32 + l) * 16);
            *(float4*)(smAh + off) = h;
            *(float4*)(smAl + off) = lo;
        }
        #pragma unroll
        for (int i = 0; i < 8; i++) {
            int pidx = wid * 8 + i;
            int s = pidx >> 4, g = pidx & 15;
            uint32_t off = (uint32_t)(((s * 16 + g) * 32 + l) * 8);
            *(float2*)(smBh + off) = make_float2(rbh[i][0], rbh[i][1]);
            *(float2*)(smBl + off) = make_float2(rbl[i][0], rbl[i][1]);
        }
        __syncthreads();
        // ---- prefetch next chunk into registers ----
        if (c + 1 < nch) {
            const int kc = (c + 1) << 5;
            #pragma unroll
            for (int i = 0; i < 4; i++) {
                int pidx = wid * 4 + i;
                int s = pidx >> 3, f = pidx & 7;
                const float* ap = Ag + (size_t)(f * 16 + r) * K + kc + s * 8 + tig;
                ra[i][0] = ap[0];
                ra[i][1] = ap[(size_t)8 * K];
                ra[i][2] = ap[4];
                ra[i][3] = ap[(size_t)8 * K + 4];
            }
            #pragma unroll
            for (int i = 0; i < 8; i++) {
                int pidx = wid * 8 + i;
                int s = pidx >> 4, g = pidx & 15;
                size_t o = (size_t)(g * 8 + r) * K + kc + s * 8 + tig;
                rbh[i][0] = Bhg[o]; rbh[i][1] = Bhg[o + 4];
                rbl[i][0] = Blg[o]; rbl[i][1] = Blg[o + 4];
            }
        }
        // ---- MMA over the 4 k-steps of this chunk ----
        #pragma unroll
        for (int s = 0; s < 4; s++) {
            uint4 ah[4], al[4];
            #pragma unroll
            for (int mf = 0; mf < 4; mf++) {
                int f = wm * 4 + mf;
                uint32_t off = (uint32_t)(((s * 8 + f) * 32 + l) * 16);
                ah[mf] = *(const uint4*)(smAh + off);
                al[mf] = *(const uint4*)(smAl + off);
            }
            #pragma unroll
            for (int nf = 0; nf < 4; nf++) {
                int g = wn * 4 + nf;
                uint32_t off = (uint32_t)(((s * 16 + g) * 32 + l) * 8);
                uint2 bh = *(const uint2*)(smBh + off);
                uint2 bl = *(const uint2*)(smBl + off);
                #pragma unroll
                for (int mf = 0; mf < 4; mf++) {
                    mma_m16n8k8_tf32(acc[mf][nf], &ah[mf].x, &bh.x);
                    mma_m16n8k8_tf32(acc[mf][nf], &ah[mf].x, &bl.x);
                    mma_m16n8k8_tf32(acc[mf][nf], &al[mf].x, &bh.x);
                }
            }
        }
    }

    // ---- epilogue: bias (+ exact GELU), write C ----
    #pragma unroll
    for (int mf = 0; mf < 4; mf++) {
        int mrow = m0 + wm * 64 + mf * 16 + r;
        #pragma unroll
        for (int nf = 0; nf < 4; nf++) {
            int col = n0 + wn * 32 + nf * 8 + tig * 2;
            float b0 = bias[col], b1 = bias[col + 1];
            float2 v0 = make_float2(acc[mf][nf][0] + b0, acc[mf][nf][1] + b1);
            float2 v1 = make_float2(acc[mf][nf][2] + b0, acc[mf][nf][3] + b1);
            if (act) {
                v0.x = gelu_exact(v0.x); v0.y = gelu_exact(v0.y);
                v1.x = gelu_exact(v1.x); v1.y = gelu_exact(v1.y);
            }
            *(float2*)(C + (size_t)mrow * Nout + col) = v0;
            *(float2*)(C + (size_t)(mrow + 8) * Nout + col) = v1;
        }
    }
}

// ------------------------------ attention -----------------------------------
// flash-style fp32. qkv buffer [tok, 2304]: q at h*64, k at 768+h*64,
// v at 1536+h*64. ctx out [tok, 768]. Fully-masked key tiles skipped.
#define ATT_PITCH 65
#define ATT_SMEM  (4 * 64 * ATT_PITCH * 4)

__global__ void __launch_bounds__(256)
attention_kernel(const float* __restrict__ qkv, const int* __restrict__ lens,
                 float* __restrict__ ctx) {
    extern __shared__ float smem[];
    float* Qs = smem;
    float* Ks = smem + 64 * ATT_PITCH;
    float* Vs = smem + 2 * 64 * ATT_PITCH;
    float* Ps = smem + 3 * 64 * ATT_PITCH;

    const int tid = threadIdx.x;
    const int tx  = tid & 15, ty = tid >> 4;
    const int qt  = blockIdx.x, hh = blockIdx.y, b = blockIdx.z;
    const int L   = lens[b];
    const size_t base  = ((size_t)b * SEQ) * DQKV + (size_t)hh * HD;
    const size_t baseo = ((size_t)b * SEQ) * DM + (size_t)hh * HD;

    for (int idx = tid; idx < 64 * 64; idx += 256) {
        int rr = idx >> 6, d = idx & 63;
        Qs[rr * ATT_PITCH + d] = qkv[base + (size_t)(qt * 64 + rr) * DQKV + d];
    }

    float acc[16];
    float mi[4], li[4];
    #pragma unroll
    for (int i = 0; i < 16; i++) acc[i] = 0.0f;
    #pragma unroll
    for (int i = 0; i < 4; i++) { mi[i] = -1e30f; li[i] = 0.0f; }

    const int ntiles = (L + 63) >> 6;
    for (int t = 0; t < ntiles; t++) {
        __syncthreads();
        for (int idx = tid; idx < 64 * 64; idx += 256) {
            int rr = idx >> 6, d = idx & 63;
            size_t g = base + (size_t)(t * 64 + rr) * DQKV + d;
            Ks[rr * ATT_PITCH + d] = qkv[g + DM];
            Vs[rr * ATT_PITCH + d] = qkv[g + 2 * DM];
        }
        __syncthreads();

        float s[16];
        #pragma unroll
        for (int i = 0; i < 16; i++) s[i] = 0.0f;
        for (int d = 0; d < 64; d++) {
            float qa[4], kb[4];
            #pragma unroll
            for (int i = 0; i < 4; i++) qa[i] = Qs[((ty << 2) + i) * ATT_PITCH + d];
            #pragma unroll
            for (int j = 0; j < 4; j++) kb[j] = Ks[((tx << 2) + j) * ATT_PITCH + d];
            #pragma unroll
            for (int i = 0; i < 4; i++)
                #pragma unroll
                for (int j = 0; j < 4; j++)
                    s[i * 4 + j] = fmaf(qa[i], kb[j], s[i * 4 + j]);
        }
        #pragma unroll
        for (int j = 0; j < 4; j++) {
            bool valid = (t * 64 + (tx << 2) + j) < L;
            #pragma unroll
            for (int i = 0; i < 4; i++)
                s[i * 4 + j] = valid ? s[i * 4 + j] * 0.125f : -1e30f;
        }
        #pragma unroll
        for (int i = 0; i < 4; i++) {
            float rm = fmaxf(fmaxf(s[i*4+0], s[i*4+1]), fmaxf(s[i*4+2], s[i*4+3]));
            #pragma unroll
            for (int o = 1; o < 16; o <<= 1)
                rm = fmaxf(rm, __shfl_xor_sync(0xffffffffu, rm, o));
            float nm = fmaxf(mi[i], rm);
            float ps = 0.0f;
            #pragma unroll
            for (int j = 0; j < 4; j++) {
                float p = __expf(s[i * 4 + j] - nm);
                s[i * 4 + j] = p;
                ps += p;
            }
            #pragma unroll
            for (int o = 1; o < 16; o <<= 1)
                ps += __shfl_xor_sync(0xffffffffu, ps, o);
            float corr = __expf(mi[i] - nm);
            li[i] = li[i] * corr + ps;
            mi[i] = nm;
            #pragma unroll
            for (int j = 0; j < 4; j++) acc[i * 4 + j] *= corr;
            #pragma unroll
            for (int j = 0; j < 4; j++)
                Ps[((ty << 2) + i) * ATT_PITCH + (tx << 2) + j] = s[i * 4 + j];
        }
        __syncthreads();
        for (int kk = 0; kk < 64; kk++) {
            float pa[4], vb[4];
            #pragma unroll
            for (int i = 0; i < 4; i++) pa[i] = Ps[((ty << 2) + i) * ATT_PITCH + kk];
            #pragma unroll
            for (int j = 0; j < 4; j++) vb[j] = Vs[kk * ATT_PITCH + (tx << 2) + j];
            #pragma unroll
            for (int i = 0; i < 4; i++)
                #pragma unroll
                for (int j = 0; j < 4; j++)
                    acc[i * 4 + j] = fmaf(pa[i], vb[j], acc[i * 4 + j]);
        }
    }

    #pragma unroll
    for (int i = 0; i < 4; i++) {
        float inv = 1.0f / li[i];
        #pragma unroll
        for (int j = 0; j < 4; j++)
            ctx[baseo + (size_t)(qt * 64 + (ty << 2) + i) * DM + (tx << 2) + j]
                = acc[i * 4 + j] * inv;
    }
}

// ----------------------- masked mean pool + L2 norm -------------------------
__global__ void pool_kernel(const float* __restrict__ h, const int* __restrict__ len,
                            float* __restrict__ out) {
    int b = blockIdx.x;
    int L = len[b];
    const float* hb = h + (size_t)b * SEQ * DM;
    float s0 = 0.0f, s1 = 0.0f, s2 = 0.0f;
    for (int t = 0; t < L; t++) {
        const float* row = hb + (size_t)t * DM;
        s0 += row[threadIdx.x];
        s1 += row[threadIdx.x + 256];
        s2 += row[threadIdx.x + 512];
    }
    float invL = 1.0f / (float)L;
    float m0 = s0 * invL, m1 = s1 * invL, m2 = s2 * invL;
    float nsq = block_reduce1(m0 * m0 + m1 * m1 + m2 * m2);
    float norm = fmaxf(sqrtf(nsq), 1e-12f);
    float inv = 1.0f / norm;
    out[b * DM + threadIdx.x]       = m0 * inv;
    out[b * DM + threadIdx.x + 256] = m1 * inv;
    out[b * DM + threadIdx.x + 512] = m2 * inv;
}

// ------------------------------- launcher -----------------------------------
extern "C" void kernel_launch(void* const* d_in, const int* in_sizes, int n_in,
                              void* d_out, int out_size) {
    (void)in_sizes; (void)n_in; (void)out_size;
    const int*   input_ids = (const int*)  d_in[0];
    const int*   amask     = (const int*)  d_in[1];
    const float* word_emb  = (const float*)d_in[2];
    const float* pos_emb   = (const float*)d_in[3];
    const float* type_emb  = (const float*)d_in[4];
    const float* emb_ln_s  = (const float*)d_in[5];
    const float* emb_ln_b  = (const float*)d_in[6];
    const float* Wq  = (const float*)d_in[7];
    const float* bq  = (const float*)d_in[8];
    const float* Wk  = (const float*)d_in[9];
    const float* bk  = (const float*)d_in[10];
    const float* Wv  = (const float*)d_in[11];
    const float* bv  = (const float*)d_in[12];
    const float* Wao = (const float*)d_in[13];
    const float* bao = (const float*)d_in[14];
    const float* l1s = (const float*)d_in[15];
    const float* l1b = (const float*)d_in[16];
    const float* Wi  = (const float*)d_in[17];
    const float* bi  = (const float*)d_in[18];
    const float* Wmo = (const float*)d_in[19];
    const float* bmo = (const float*)d_in[20];
    const float* l2s = (const float*)d_in[21];
    const float* l2b = (const float*)d_in[22];

    float *h, *qkv, *cx, *t1, *ao, *inter, *bqkv;
    float *qkvh, *qkvl, *oh, *ol, *ih, *il, *moh, *mol;
    int* len;
    cudaGetSymbolAddress((void**)&h,     g_h);
    cudaGetSymbolAddress((void**)&qkv,   g_qkv);
    cudaGetSymbolAddress((void**)&cx,    g_ctx);
    cudaGetSymbolAddress((void**)&t1,    g_t1);
    cudaGetSymbolAddress((void**)&ao,    g_ao);
    cudaGetSymbolAddress((void**)&inter, g_int);
    cudaGetSymbolAddress((void**)&len,   g_len);
    cudaGetSymbolAddress((void**)&bqkv,  g_bqkv);
    cudaGetSymbolAddress((void**)&qkvh,  g_qkvh);
    cudaGetSymbolAddress((void**)&qkvl,  g_qkvl);
    cudaGetSymbolAddress((void**)&oh,    g_oh);
    cudaGetSymbolAddress((void**)&ol,    g_ol);
    cudaGetSymbolAddress((void**)&ih,    g_ih);
    cudaGetSymbolAddress((void**)&il,    g_il);
    cudaGetSymbolAddress((void**)&moh,   g_moh);
    cudaGetSymbolAddress((void**)&mol,   g_mol);

    cudaFuncSetAttribute(attention_kernel,
                         cudaFuncAttributeMaxDynamicSharedMemorySize, ATT_SMEM);
    cudaFuncSetAttribute(gemm_mma_kernel,
                         cudaFuncAttributeMaxDynamicSharedMemorySize, GEMM_SMEM_MMA);

    // ---- preprocessing: transpose + tf32-split all weights ----
    {
        dim3 gdd(DM / 32, DM / 32, NL);
        transpose_split_kernel<<<gdd, 256>>>(Wq, qkvh,                qkvl,
                                             DM, DM, (size_t)DM * DM, (size_t)DQKV * DM);
        transpose_split_kernel<<<gdd, 256>>>(Wk, qkvh + DM * DM,      qkvl + DM * DM,
                                             DM, DM, (size_t)DM * DM, (size_t)DQKV * DM);
        transpose_split_kernel<<<gdd, 256>>>(Wv, qkvh + 2 * DM * DM,  qkvl + 2 * DM * DM,
                                             DM, DM, (size_t)DM * DM, (size_t)DQKV * DM);
        transpose_split_kernel<<<gdd, 256>>>(Wao, oh, ol,
                                             DM, DM, (size_t)DM * DM, (size_t)DM * DM);
        dim3 gdf(DFF / 32, DM / 32, NL);
        transpose_split_kernel<<<gdf, 256>>>(Wi, ih, il,
                                             DM, DFF, (size_t)DM * DFF, (size_t)DFF * DM);
        dim3 gfd(DM / 32, DFF / 32, NL);
        transpose_split_kernel<<<gfd, 256>>>(Wmo, moh, mol,
                                             DFF, DM, (size_t)DFF * DM, (size_t)DM * DFF);
        biaspack_kernel<<<NL, 256>>>(bq, bk, bv, bqkv);
    }

    embed_ln_kernel<<<NTOK, 256>>>(input_ids, word_emb, pos_emb, type_emb,
                                   emb_ln_s, emb_ln_b, h);
    length_kernel<<<NB, 256>>>(amask, len);

    dim3 gQKV(DQKV / 128, NTOK / 128);   // 18 x 64
    dim3 gD  (DM   / 128, NTOK / 128);   // 6 x 64
    dim3 gF  (DFF  / 128, NTOK / 128);   // 24 x 64
    dim3 gA  (SEQ / 64, NH, NB);

    for (int l = 0; l < NL; l++) {
        const size_t wq_off = (size_t)l * DQKV * DM;
        const size_t wo_off = (size_t)l * DM * DM;
        const size_t wi_off = (size_t)l * DFF * DM;
        const size_t wm_off = (size_t)l * DM * DFF;

        gemm_mma_kernel<<<gQKV, 256, GEMM_SMEM_MMA>>>(h, qkvh + wq_off, qkvl + wq_off,
                                                      bqkv + l * DQKV, qkv, DM, DQKV, 0);
        attention_kernel<<<gA, 256, ATT_SMEM>>>(qkv, len, cx);

        gemm_mma_kernel<<<gD, 256, GEMM_SMEM_MMA>>>(cx, oh + wo_off, ol + wo_off,
                                                    bao + l * DM, t1, DM, DM, 0);
        add_ln_kernel<<<NTOK, 256>>>(t1, h, l1s + l * DM, l1b + l * DM, ao);

        gemm_mma_kernel<<<gF, 256, GEMM_SMEM_MMA>>>(ao, ih + wi_off, il + wi_off,
                                                    bi + l * DFF, inter, DM, DFF, 1);
        gemm_mma_kernel<<<gD, 256, GEMM_SMEM_MMA>>>(inter, moh + wm_off, mol + wm_off,
                                                    bmo + l * DM, t1, DFF, DM, 0);
        add_ln_kernel<<<NTOK, 256>>>(t1, ao, l2s + l * DM, l2b + l * DM, h);
    }

    pool_kernel<<<NB, 256>>>(h, len, (float*)d_out);
}